// round 8
// baseline (speedup 1.0000x reference)
#include <cuda_runtime.h>
#include <math.h>

// Problem constants
#define B_TOT 256
#define AIN   8
#define MUL   1024
#define NK    20
#define NO    16
#define PL2   528            // half-plane stride in floats (16B aligned, conflict-free)

// Persistent scratch (device globals; allocation-free)
__device__ __align__(16) float g_c[NK * MUL];
__device__ __align__(16) float g_b[NK * MUL];
__device__ __align__(16) float g_bpart[16 * NK * MUL];
__device__ __align__(16) float g_xt[B_TOT * MUL * AIN];   // x transposed [b][a][m]
__device__ __align__(16) float g_yp[B_TOT * 2 * AIN];     // prep partial plane sums [b][mh][a]
__device__ __align__(16) float g_yh[B_TOT * 2 * NK * AIN];// y partials [b][mh][k][a]

// Packed f32x2 FMA
#define FMA2(acc, a, b) \
    asm("fma.rn.f32x2 %0, %1, %2, %0;" : "+l"(acc) : "l"(a), "l"(b))

__device__ __forceinline__ float pair_sum(unsigned long long u) {
    float lo = __uint_as_float((unsigned)(u & 0xffffffffu));
    float hi = __uint_as_float((unsigned)(u >> 32));
    return lo + hi;
}

#define WARP_RED_SUM(v)                                   \
  do {                                                    \
    v += __shfl_xor_sync(0xffffffffu, v, 16);             \
    v += __shfl_xor_sync(0xffffffffu, v, 8);              \
    v += __shfl_xor_sync(0xffffffffu, v, 4);              \
    v += __shfl_xor_sync(0xffffffffu, v, 2);              \
    v += __shfl_xor_sync(0xffffffffu, v, 1);              \
  } while (0)

// ---------------------------------------------------------------------------
// Prep: 512 blocks = (batch, m-half). Transpose x half into g_xt[b][a][m]
// and emit partial plane sums g_yp[b][mh][a] (for iteration-0 uniform-c y).
// ---------------------------------------------------------------------------
#define A_THREADS 256

__global__ void __launch_bounds__(A_THREADS)
prep_kernel(const float* __restrict__ x)
{
    __shared__ float xsm[512 * 9];            // padded rows [m_local][9]
    const int tid = threadIdx.x;
    const int B = blockIdx.x;
    const int b = B >> 1, mh = B & 1;

    const float4* xsrc = (const float4*)(x + (size_t)b * 8192 + mh * 4096);
    for (int i = tid; i < 1024; i += A_THREADS) {
        float4 v = xsrc[i];
        int m = i >> 1, h = i & 1;
        float* d = xsm + m * 9 + h * 4;
        d[0] = v.x; d[1] = v.y; d[2] = v.z; d[3] = v.w;
    }
    __syncthreads();

    float4* xdst = (float4*)(g_xt + (size_t)b * 8192);
    for (int i = tid; i < 1024; i += A_THREADS) {
        int a = i >> 7, q = i & 127, m4 = q * 4;
        float4 v;
        v.x = xsm[(m4 + 0) * 9 + a];
        v.y = xsm[(m4 + 1) * 9 + a];
        v.z = xsm[(m4 + 2) * 9 + a];
        v.w = xsm[(m4 + 3) * 9 + a];
        xdst[a * 256 + mh * 128 + q] = v;
    }

    // partial plane sums (8 warps == 8 atoms)
    const int w = tid >> 5, lane = tid & 31;
    float s = 0.f;
    #pragma unroll
    for (int t = 0; t < 16; t++) s += xsm[(t * 32 + lane) * 9 + w];
    WARP_RED_SUM(s);
    if (lane == 0) g_yp[b * 16 + mh * 8 + w] = s;
}

// ---------------------------------------------------------------------------
// Y kernel: 512 blocks = (batch, m-half). y-partial = c^T x over the half.
// warp = (kquad, a-half); acc[4][4] u64 (32 regs). Writes g_yh[b][mh][k][a].
// ---------------------------------------------------------------------------
#define Y_THREADS 320

__global__ void __launch_bounds__(Y_THREADS, 3)
y_kernel()
{
    __shared__ float xs[AIN * PL2];           // 16.9 KB half-planes [a][m_local]
    const int tid = threadIdx.x;
    const int B = blockIdx.x;                 // b*2 + mh
    const int b = B >> 1, mh = B & 1;

    {
        const float4* xsrc = (const float4*)(g_xt + (size_t)b * 8192);
        for (int i = tid; i < 1024; i += Y_THREADS) {
            int a = i >> 7, q = i & 127;
            *(float4*)(xs + a * PL2 + q * 4) = xsrc[a * 256 + mh * 128 + q];
        }
    }
    __syncthreads();

    const int w = tid >> 5, lane = tid & 31;
    const int k0 = (w >> 1) * 4;
    const int a0 = (w & 1) * 4;

    unsigned long long acc[4][4];
    #pragma unroll
    for (int kk = 0; kk < 4; kk++)
        #pragma unroll
        for (int aa = 0; aa < 4; aa++) acc[kk][aa] = 0ull;

    #pragma unroll 1
    for (int j = 0; j < 4; j++) {
        const int ml = j * 128 + lane * 4;
        const int mg = mh * 512 + ml;
        ulonglong2 ck0 = *(const ulonglong2*)(g_c + (k0 + 0) * MUL + mg);
        ulonglong2 ck1 = *(const ulonglong2*)(g_c + (k0 + 1) * MUL + mg);
        ulonglong2 ck2 = *(const ulonglong2*)(g_c + (k0 + 2) * MUL + mg);
        ulonglong2 ck3 = *(const ulonglong2*)(g_c + (k0 + 3) * MUL + mg);
        #pragma unroll
        for (int aa = 0; aa < 4; aa++) {
            ulonglong2 xv = *(const ulonglong2*)(xs + (a0 + aa) * PL2 + ml);
            FMA2(acc[0][aa], ck0.x, xv.x); FMA2(acc[0][aa], ck0.y, xv.y);
            FMA2(acc[1][aa], ck1.x, xv.x); FMA2(acc[1][aa], ck1.y, xv.y);
            FMA2(acc[2][aa], ck2.x, xv.x); FMA2(acc[2][aa], ck2.y, xv.y);
            FMA2(acc[3][aa], ck3.x, xv.x); FMA2(acc[3][aa], ck3.y, xv.y);
        }
    }
    #pragma unroll
    for (int kk = 0; kk < 4; kk++) {
        #pragma unroll
        for (int aa = 0; aa < 4; aa++) {
            float v = pair_sum(acc[kk][aa]);
            WARP_RED_SUM(v);
            if (lane == 0)
                g_yh[(size_t)B * 160 + (k0 + kk) * 8 + a0 + aa] = v;
        }
    }
}

// ---------------------------------------------------------------------------
// U' kernel: 256 blocks = (16 m-tiles x 16 slices). HEAD: tail-of-F for this
// slice's 16 batches (y-combine -> s -> squash -> v -> wv, all in smem).
// BODY: agree partial[m,k] = sum_{b in slice} sum_a x*wv / 256 -> g_bpart.
// Dynamic smem layout (floats):
//   wvs [0,2560)   ssm [2560,7680)   ysm [7680,10240)   csm [10240,10496)
//   xsU [2560,6656)  (reuses ssm region after the tail; barrier-separated)
// ---------------------------------------------------------------------------
#define U_THREADS 320
#define U_SMEM    (10496 * 4)

__global__ void __launch_bounds__(U_THREADS)
update_kernel(const float* __restrict__ x, const float* __restrict__ W, int iter)
{
    extern __shared__ float sm[];
    float* wvs = sm;                // [16][160]
    float* ssm = sm + 2560;         // [16][320]
    float* ysm = sm + 7680;         // [16][160] (iter>=1) / [16][8] (iter 0)
    float* csm = sm + 10240;        // [16][16]
    float* xsU = sm + 2560;         // [8][512] staging (after tail)

    const int tid   = threadIdx.x;
    const int m0    = blockIdx.x * 64;
    const int bbase = blockIdx.y * 16;

    // ---- tail head: build y for the slice ----
    if (iter == 0) {
        if (tid < 128) {
            int bb = tid >> 3, a = tid & 7;
            ysm[bb * 8 + a] = (g_yp[(bbase + bb) * 16 + a]
                             + g_yp[(bbase + bb) * 16 + 8 + a]) * (1.0f / 1024.0f);
        }
    } else {
        for (int i = tid; i < 2560; i += U_THREADS) {
            int bb = i / 160, r = i % 160;
            size_t base = (size_t)(bbase + bb) * 2 * 160;
            ysm[i] = g_yh[base + r] + g_yh[base + 160 + r];
        }
    }
    __syncthreads();

    // s: thread = (k,o) = tid, loop over 16 batches
    {
        float wreg[8];
        #pragma unroll
        for (int a = 0; a < 8; a++) wreg[a] = W[tid * 8 + a];
        const int k = tid >> 4;
        #pragma unroll
        for (int bb = 0; bb < 16; bb++) {
            const float* y = (iter == 0) ? (ysm + bb * 8) : (ysm + bb * 160 + k * 8);
            float s = 0.f;
            #pragma unroll
            for (int a = 0; a < 8; a++) s += wreg[a] * y[a];
            ssm[bb * 320 + tid] = s;
        }
    }
    __syncthreads();

    // squash coefficients (sum over classes, per reference)
    if (tid < 256) {
        int bb = tid >> 4, o = tid & 15;
        float msq = 0.f;
        #pragma unroll
        for (int kk = 0; kk < NK; kk++) {
            float t = ssm[bb * 320 + kk * 16 + o];
            msq += t * t;
        }
        csm[tid] = msq / ((1.f + msq) * sqrtf(msq));
    }
    __syncthreads();

    // v = coeff * s (in place)
    {
        const int o = tid & 15;
        #pragma unroll
        for (int bb = 0; bb < 16; bb++)
            ssm[bb * 320 + tid] *= csm[bb * 16 + o];
    }
    __syncthreads();

    // wv[b][k][a] = sum_o W[k,o,a] * v[b,k,o]
    {
        const int r   = tid % 160;
        const int bb0 = tid / 160;           // 0 or 1
        const int kk  = r >> 3, aa = r & 7;
        float w16[16];
        #pragma unroll
        for (int oo = 0; oo < 16; oo++) w16[oo] = W[(kk * 16 + oo) * 8 + aa];
        #pragma unroll
        for (int s8 = 0; s8 < 8; s8++) {
            int bb = bb0 + s8 * 2;
            float acc = 0.f;
            #pragma unroll
            for (int oo = 0; oo < 16; oo++)
                acc += w16[oo] * ssm[bb * 320 + kk * 16 + oo];
            wvs[bb * 160 + r] = acc;
        }
    }

    // ---- agree partial loop ----
    const int mi4 = tid / NK;
    const int k   = tid % NK;
    unsigned long long acc[4];
    #pragma unroll
    for (int i = 0; i < 4; i++) acc[i] = 0ull;

    for (int c0 = 0; c0 < 16; c0 += 8) {
        __syncthreads();                      // also orders tail-ssm vs xsU reuse
        for (int i = tid; i < 1024; i += U_THREADS) {
            int bi = i >> 7, rr = i & 127;
            ((float4*)(xsU + bi * 512))[rr] =
                ((const float4*)(x + (size_t)(bbase + c0 + bi) * 8192 + m0 * 8))[rr];
        }
        __syncthreads();

        #pragma unroll
        for (int bi = 0; bi < 8; bi++) {
            const ulonglong2* wp = (const ulonglong2*)(wvs + (c0 + bi) * 160 + k * 8);
            ulonglong2 wA = wp[0], wB = wp[1];
            const ulonglong2* xp = (const ulonglong2*)(xsU + bi * 512 + mi4 * 32);
            #pragma unroll
            for (int mm = 0; mm < 4; mm++) {
                ulonglong2 xA = xp[mm * 2];
                ulonglong2 xB = xp[mm * 2 + 1];
                FMA2(acc[mm], xA.x, wA.x);
                FMA2(acc[mm], xA.y, wA.y);
                FMA2(acc[mm], xB.x, wB.x);
                FMA2(acc[mm], xB.y, wB.y);
            }
        }
    }

    float* dst = g_bpart + (size_t)blockIdx.y * (NK * MUL) + k * MUL + m0 + mi4 * 4;
    #pragma unroll
    for (int mm = 0; mm < 4; mm++) dst[mm] = pair_sum(acc[mm]) * (1.0f / 256.0f);
}

// ---------------------------------------------------------------------------
// Softmax kernel: 20 blocks x 1024 threads (thread per m).
// ---------------------------------------------------------------------------
__global__ void __launch_bounds__(1024)
softmax_kernel(int accum)
{
    const int k = blockIdx.x;
    const int t = threadIdx.x;
    const int lane = t & 31, wp = t >> 5;
    __shared__ float red[32];
    __shared__ float bc;

    float b = accum ? g_b[k * MUL + t] : 0.f;
    #pragma unroll
    for (int p = 0; p < 16; p++) b += g_bpart[p * NK * MUL + k * MUL + t];
    g_b[k * MUL + t] = b;

    float mx = b;
    #pragma unroll
    for (int off = 16; off; off >>= 1)
        mx = fmaxf(mx, __shfl_xor_sync(0xffffffffu, mx, off));
    if (lane == 0) red[wp] = mx;
    __syncthreads();
    if (t < 32) {
        float m = red[t];
        #pragma unroll
        for (int off = 16; off; off >>= 1)
            m = fmaxf(m, __shfl_xor_sync(0xffffffffu, m, off));
        if (t == 0) bc = m;
    }
    __syncthreads();
    mx = bc;

    float e = expf(b - mx);
    float s = e;
    #pragma unroll
    for (int off = 16; off; off >>= 1)
        s += __shfl_xor_sync(0xffffffffu, s, off);
    __syncthreads();
    if (lane == 0) red[wp] = s;
    __syncthreads();
    if (t < 32) {
        float ss = red[t];
        #pragma unroll
        for (int off = 16; off; off >>= 1)
            ss += __shfl_xor_sync(0xffffffffu, ss, off);
        if (t == 0) bc = ss;
    }
    __syncthreads();

    g_c[k * MUL + t] = e * (1.0f / bc);
}

// ---------------------------------------------------------------------------
// OUT kernel: final squash from y-halves -> output. 256 blocks x 320 threads.
// ---------------------------------------------------------------------------
__global__ void __launch_bounds__(320)
out_kernel(const float* __restrict__ W, float* __restrict__ out)
{
    __shared__ float ysm[NK * AIN];
    __shared__ float ssm[NK * NO];
    __shared__ float csm[NO];
    const int tid = threadIdx.x;
    const int b   = blockIdx.x;

    if (tid < 160) {
        size_t base = (size_t)b * 2 * 160;
        ysm[tid] = g_yh[base + tid] + g_yh[base + 160 + tid];
    }
    __syncthreads();

    const int k = tid >> 4, o = tid & 15;
    float s = 0.f;
    #pragma unroll
    for (int a = 0; a < 8; a++) s += W[tid * 8 + a] * ysm[k * 8 + a];
    ssm[tid] = s;
    __syncthreads();

    if (tid < NO) {
        float msq = 0.f;
        #pragma unroll
        for (int kk = 0; kk < NK; kk++) {
            float t = ssm[kk * NO + tid];
            msq += t * t;
        }
        csm[tid] = msq / ((1.f + msq) * sqrtf(msq));
    }
    __syncthreads();

    out[(size_t)b * 320 + tid] = csm[o] * s;
}

// ---------------------------------------------------------------------------
extern "C" void kernel_launch(void* const* d_in, const int* in_sizes, int n_in,
                              void* d_out, int out_size)
{
    const float* x = (const float*)d_in[0];   // [256][1024][8] flat view
    const float* W = (const float*)d_in[1];   // [20][16][8]
    float* out = (float*)d_out;               // [256][20][16][1]

    cudaFuncSetAttribute(update_kernel,
                         cudaFuncAttributeMaxDynamicSharedMemorySize, U_SMEM);

    dim3 ugrid(16, 16);

    // prep: transpose + iter-0 partial plane sums
    prep_kernel<<<512, A_THREADS>>>(x);
    // iter 0: tail (uniform-c y) + agree partials, then softmax
    update_kernel<<<ugrid, U_THREADS, U_SMEM>>>(x, W, 0);
    softmax_kernel<<<NK, 1024>>>(0);
    // iter 1
    y_kernel<<<512, Y_THREADS>>>();
    update_kernel<<<ugrid, U_THREADS, U_SMEM>>>(x, W, 1);
    softmax_kernel<<<NK, 1024>>>(1);
    // iter 2 (final)
    y_kernel<<<512, Y_THREADS>>>();
    out_kernel<<<256, 320>>>(W, out);
}